// round 1
// baseline (speedup 1.0000x reference)
#include <cuda_runtime.h>

#define FULLMASK 0xffffffffu
#define H 128
#define NP 512
#define NVOX 50000
#define NEDGE 800000
#define SLOPE 0.01f

// ---------------- device scratch (static, allocation-free) ----------------
__device__ float g_xproj[NP * H];                 // 256 KB
__device__ float g_vproj[(long long)NVOX * H];    // 25.6 MB
__device__ float g_yexp[NEDGE];                   // 3.2 MB
__device__ float g_part[8192];
__device__ float g_invS;

// tanh with ~1e-7 absolute error: 1 mul + EX2 + add/sub + RCP + mul (2 MUFU)
__device__ __forceinline__ float fast_tanh(float x) {
    float e = __expf(2.0f * x);
    return __fdividef(e - 1.0f, e + 1.0f);
}

// ---------------- K1: x_proj = x @ W_program + b_program  [512 x 128] ----------------
__global__ __launch_bounds__(256) void k1_xproj(const float* __restrict__ x,
                                                const float* __restrict__ Wp,
                                                const float* __restrict__ bp) {
    int warp = threadIdx.x >> 5, lane = threadIdx.x & 31;
    int row = blockIdx.x * 8 + warp;
    if (row >= NP) return;
    float4 xv = *(const float4*)(x + row * H + lane * 4);
    float4 acc = *(const float4*)(bp + lane * 4);
#pragma unroll
    for (int k0 = 0; k0 < 32; ++k0) {
        float a0 = __shfl_sync(FULLMASK, xv.x, k0);
        float a1 = __shfl_sync(FULLMASK, xv.y, k0);
        float a2 = __shfl_sync(FULLMASK, xv.z, k0);
        float a3 = __shfl_sync(FULLMASK, xv.w, k0);
        const float* wr = Wp + (k0 * 4) * H + lane * 4;
        float4 w0 = *(const float4*)(wr);
        float4 w1 = *(const float4*)(wr + H);
        float4 w2 = *(const float4*)(wr + 2 * H);
        float4 w3 = *(const float4*)(wr + 3 * H);
        acc.x = fmaf(a0, w0.x, fmaf(a1, w1.x, fmaf(a2, w2.x, fmaf(a3, w3.x, acc.x))));
        acc.y = fmaf(a0, w0.y, fmaf(a1, w1.y, fmaf(a2, w2.y, fmaf(a3, w3.y, acc.y))));
        acc.z = fmaf(a0, w0.z, fmaf(a1, w1.z, fmaf(a2, w2.z, fmaf(a3, w3.z, acc.z))));
        acc.w = fmaf(a0, w0.w, fmaf(a1, w1.w, fmaf(a2, w2.w, fmaf(a3, w3.w, acc.w))));
    }
    *(float4*)(g_xproj + row * H + lane * 4) = acc;
}

// ---------------- K2: fused dual GEMM on v ----------------
// v_proj = v@Wv + bv  AND  a = v@Wm1 + bm1 -> lrelu -> mask = sigmoid(a@Wm2 + bm2)
// Block: 64 rows, both weight matrices resident in smem (128 KB). 8x(4+4) reg tile.
__global__ __launch_bounds__(256, 1) void k2_vside(const float* __restrict__ v,
                                                   const float* __restrict__ Wv,
                                                   const float* __restrict__ bv,
                                                   const float* __restrict__ Wm1,
                                                   const float* __restrict__ bm1,
                                                   const float* __restrict__ Wm2,
                                                   const float* __restrict__ bm2,
                                                   float* __restrict__ mask_out) {
    extern __shared__ float smem[];
    float* sW = smem;            // [128][256] : cols 0..127 = Wv, 128..255 = Wm1
    float* sv = smem + 32768;    // [64][128]
    float* sb = sv + 8192;       // 256 biases (bv | bm1)
    float* sm2 = sb + 256;       // Wm2 (128)

    int tid = threadIdx.x;
    int d0 = blockIdx.x * 64;

    // stage W (both matrices)
    for (int s = tid; s < 8192; s += 256) {
        int k = s >> 6, jq = s & 63;
        float4 w = (jq < 32) ? *(const float4*)(Wv + k * H + jq * 4)
                             : *(const float4*)(Wm1 + k * H + (jq - 32) * 4);
        *(float4*)(sW + k * 256 + jq * 4) = w;
    }
    if (tid < 128) { sb[tid] = bv[tid]; sb[128 + tid] = bm1[tid]; sm2[tid] = Wm2[tid]; }
    // stage v tile (coalesced; clamp for tail block)
    for (int s = tid; s < 2048; s += 256) {
        int r = s >> 5, q = s & 31;
        int gr = d0 + r; if (gr >= NVOX) gr = NVOX - 1;
        *(float4*)(sv + r * H + q * 4) = *(const float4*)(v + (long long)gr * H + q * 4);
    }
    __syncthreads();

    int ty = tid >> 5, tx = tid & 31;   // warp = 8 rows, lane = 4+4 cols
    float accV[8][4], accA[8][4];
#pragma unroll
    for (int i = 0; i < 8; ++i)
#pragma unroll
        for (int c = 0; c < 4; ++c) {
            accV[i][c] = sb[tx * 4 + c];
            accA[i][c] = sb[128 + tx * 4 + c];
        }

#pragma unroll 4
    for (int k = 0; k < H; ++k) {
        float4 b0 = *(const float4*)(sW + k * 256 + tx * 4);
        float4 b1 = *(const float4*)(sW + k * 256 + 128 + tx * 4);
#pragma unroll
        for (int i = 0; i < 8; ++i) {
            float a = sv[(ty * 8 + i) * H + k];   // warp-uniform broadcast LDS
            accV[i][0] = fmaf(a, b0.x, accV[i][0]);
            accV[i][1] = fmaf(a, b0.y, accV[i][1]);
            accV[i][2] = fmaf(a, b0.z, accV[i][2]);
            accV[i][3] = fmaf(a, b0.w, accV[i][3]);
            accA[i][0] = fmaf(a, b1.x, accA[i][0]);
            accA[i][1] = fmaf(a, b1.y, accA[i][1]);
            accA[i][2] = fmaf(a, b1.z, accA[i][2]);
            accA[i][3] = fmaf(a, b1.w, accA[i][3]);
        }
    }

    // epilogue 1: v_proj
#pragma unroll
    for (int i = 0; i < 8; ++i) {
        int gr = d0 + ty * 8 + i;
        if (gr < NVOX) {
            float4 o = make_float4(accV[i][0], accV[i][1], accV[i][2], accV[i][3]);
            *(float4*)(g_vproj + (long long)gr * H + tx * 4) = o;
        }
    }
    // epilogue 2: mask = sigmoid(lrelu(a) @ Wm2 + bm2)  (warp-wide reduce over 128 cols)
    float bm2v = bm2[0];
#pragma unroll
    for (int i = 0; i < 8; ++i) {
        float p = 0.0f;
#pragma unroll
        for (int c = 0; c < 4; ++c) {
            float a = accA[i][c];
            a = (a >= 0.0f) ? a : SLOPE * a;
            p = fmaf(a, sm2[tx * 4 + c], p);
        }
#pragma unroll
        for (int off = 16; off; off >>= 1) p += __shfl_xor_sync(FULLMASK, p, off);
        if (tx == 0) {
            int gr = d0 + ty * 8 + i;
            if (gr < NVOX) mask_out[gr] = 1.0f / (1.0f + expf(-(p + bm2v)));
        }
    }
}

// ---------------- K3: edge logits + gumbel + exp, per-voxel warp ----------------
__global__ __launch_bounds__(256) void k3_logits(const int* __restrict__ src,
                                                 const float* __restrict__ gu,
                                                 const float* __restrict__ theta) {
    int warp = threadIdx.x >> 5, lane = threadIdx.x & 31;
    int d = blockIdx.x * 8 + warp;          // grid = 6250, exactly covers 50000
    float4 vp = *(const float4*)(g_vproj + (long long)d * H + lane * 4);
    float4 th = *(const float4*)(theta + lane * 4);
    int sj = 0; float uj = 0.5f;
    if (lane < 16) {
        sj = src[d + lane * NVOX];
        uj = gu[d + lane * NVOX];
    }
    float yex = 0.0f;
#pragma unroll
    for (int j = 0; j < 16; ++j) {
        int s = __shfl_sync(FULLMASK, sj, j);
        float4 xp = *(const float4*)(g_xproj + s * H + lane * 4);
        float p;
        p = th.x * fast_tanh(xp.x + vp.x);
        p = fmaf(th.y, fast_tanh(xp.y + vp.y), p);
        p = fmaf(th.z, fast_tanh(xp.z + vp.z), p);
        p = fmaf(th.w, fast_tanh(xp.w + vp.w), p);
#pragma unroll
        for (int off = 16; off; off >>= 1) p += __shfl_xor_sync(FULLMASK, p, off);
        if (lane == j) {
            // accurate log/exp here: argmax-critical path (TAU = 1)
            float g = -logf(-logf(uj));
            yex = expf(p + g);
        }
    }
    if (lane < 16) g_yexp[d + lane * NVOX] = yex;
    // deterministic partial sum of exp
    float t = yex;
#pragma unroll
    for (int off = 16; off; off >>= 1) t += __shfl_xor_sync(FULLMASK, t, off);
    __shared__ float sred[8];
    if (lane == 0) sred[warp] = t;
    __syncthreads();
    if (threadIdx.x == 0) {
        float s = 0.0f;
#pragma unroll
        for (int i = 0; i < 8; ++i) s += sred[i];
        g_part[blockIdx.x] = s;
    }
}

// ---------------- K3b: combine partials, invS ----------------
__global__ void k3b_reduce(int n) {
    int tid = threadIdx.x;
    float s = 0.0f;
    for (int i = tid; i < n; i += 256) s += g_part[i];
#pragma unroll
    for (int off = 16; off; off >>= 1) s += __shfl_xor_sync(FULLMASK, s, off);
    __shared__ float sr[8];
    if ((tid & 31) == 0) sr[tid >> 5] = s;
    __syncthreads();
    if (tid == 0) {
        float t = 0.0f;
        for (int i = 0; i < 8; ++i) t += sr[i];
        g_invS = 1.0f / t;
    }
}

// ---------------- K4: y, y_hard (first-argmax), scatter-sum, v_out ----------------
__global__ __launch_bounds__(256) void k4_final(const float* __restrict__ x,
                                                const float* __restrict__ v,
                                                const int* __restrict__ src,
                                                const float* __restrict__ mask_arr,
                                                float* __restrict__ vout,
                                                float* __restrict__ y_out,
                                                float* __restrict__ yh_out) {
    int warp = threadIdx.x >> 5, lane = threadIdx.x & 31;
    int d = blockIdx.x * 8 + warp;          // grid = 6250
    float invS = g_invS;
    float ye = 0.0f; int sj = 0;
    if (lane < 16) {
        ye = g_yexp[d + lane * NVOX] * invS;
        sj = src[d + lane * NVOX];
        y_out[d + lane * NVOX] = ye;
    }
    // first-max argmax over this voxel's 16 edges (matches reference tie semantics)
    float mv = (lane < 16) ? ye : -1.0f;
    int mi = lane;
#pragma unroll
    for (int off = 16; off; off >>= 1) {
        float ov = __shfl_xor_sync(FULLMASK, mv, off);
        int oi = __shfl_xor_sync(FULLMASK, mi, off);
        if (ov > mv || (ov == mv && oi < mi)) { mv = ov; mi = oi; }
    }
    if (lane < 16) yh_out[d + lane * NVOX] = (lane == mi) ? 1.0f : 0.0f;

    float md = mask_arr[d];
    float ax = 0.0f, ay = 0.0f, az = 0.0f, aw = 0.0f;
#pragma unroll
    for (int j = 0; j < 16; ++j) {
        float yj = __shfl_sync(FULLMASK, ye, j);
        int s = __shfl_sync(FULLMASK, sj, j);
        float4 x4 = *(const float4*)(x + s * H + lane * 4);
        ax = fmaf(yj, x4.x, ax);
        ay = fmaf(yj, x4.y, ay);
        az = fmaf(yj, x4.z, az);
        aw = fmaf(yj, x4.w, aw);
    }
    float4 v4 = *(const float4*)(v + (long long)d * H + lane * 4);
    float4 o;
    o.x = fmaf(md, ax, v4.x);
    o.y = fmaf(md, ay, v4.y);
    o.z = fmaf(md, az, v4.z);
    o.w = fmaf(md, aw, v4.w);
    *(float4*)(vout + (long long)d * H + lane * 4) = o;
}

// ---------------- launch ----------------
extern "C" void kernel_launch(void* const* d_in, const int* in_sizes, int n_in,
                              void* d_out, int out_size) {
    const float* x    = (const float*)d_in[0];
    const float* v    = (const float*)d_in[1];
    const int*   cei  = (const int*)d_in[2];     // [2, E]; row0 = src
    const float* Wp   = (const float*)d_in[3];
    const float* bp   = (const float*)d_in[4];
    const float* Wv   = (const float*)d_in[5];
    const float* bv   = (const float*)d_in[6];
    const float* Wm1  = (const float*)d_in[7];
    const float* bm1  = (const float*)d_in[8];
    const float* Wm2  = (const float*)d_in[9];
    const float* bm2  = (const float*)d_in[10];
    const float* th   = (const float*)d_in[11];
    const float* gu   = (const float*)d_in[12];
    const int* src = cei;

    float* out      = (float*)d_out;
    float* vout     = out;                                  // NV*H
    float* mask_out = out + (long long)NVOX * H;            // NV
    float* y_out    = mask_out + NVOX;                      // E
    float* yh_out   = y_out + NEDGE;                        // E

    k1_xproj<<<NP / 8, 256>>>(x, Wp, bp);

    int smemK2 = (32768 + 8192 + 256 + 128) * 4;            // 165376 B
    cudaFuncSetAttribute(k2_vside, cudaFuncAttributeMaxDynamicSharedMemorySize, smemK2);
    k2_vside<<<(NVOX + 63) / 64, 256, smemK2>>>(v, Wv, bv, Wm1, bm1, Wm2, bm2, mask_out);

    int nblk3 = NVOX / 8;                                   // 6250
    k3_logits<<<nblk3, 256>>>(src, gu, th);
    k3b_reduce<<<1, 256>>>(nblk3);
    k4_final<<<nblk3, 256>>>(x, v, src, mask_out, vout, y_out, yh_out);
}